// round 16
// baseline (speedup 1.0000x reference)
#include <cuda_runtime.h>
#include <cuda_bf16.h>
#include <cuda_fp16.h>
#include <math.h>
#include <stdint.h>

#define B_  8
#define C_  512
#define L_  8192
#define H_  4
#define HID 128
#define O3  384   // rows in w_qkv: [0,128)=q, [128,256)=k, [256,384)=v
#define NCH 32    // ctx column chunks
#define CHL (L_ / NCH)     // 256 columns per chunk
#define CT  (CHL / 64)     // 4 tiles of 64 cols per chunk

// Scratch (static device arrays — no runtime allocation)
__device__ float g_pn [(size_t)B_ * H_ * NCH * 32 * 32];
__device__ float g_pd [(size_t)B_ * H_ * NCH * 32];
__device__ float g_ctx[(size_t)B_ * H_ * 32 * 32];
__device__ __half g_wh16[(size_t)O3 * C_];              // w_qkv hi (fp16)
__device__ __half g_wl16[(size_t)O3 * C_];              // w_qkv lo (fp16)
__device__ __half g_xf [(size_t)B_ * C_ * L_];          // x fp16 (single)
__device__ __nv_bfloat16 g_qh [(size_t)B_ * HID * L_];
__device__ __nv_bfloat16 g_ql [(size_t)B_ * HID * L_];
__device__ __half g_kb [(size_t)B_ * HID * L_];         // exp(k) fp16
__device__ __half g_vb [(size_t)B_ * HID * L_];         // v fp16
__device__ __nv_bfloat16 g_W2h[(size_t)B_ * C_ * HID];
__device__ __nv_bfloat16 g_W2l[(size_t)B_ * C_ * HID];

// ---------------------------- helpers --------------------------------------
__device__ __forceinline__ uint32_t smem_u32(const void* p){
    uint32_t a;
    asm("{ .reg .u64 t; cvta.to.shared.u64 t, %1; cvt.u32.u64 %0, t; }"
        : "=r"(a) : "l"(p));
    return a;
}
__device__ __forceinline__ void cp16(uint32_t saddr, const void* g){
    asm volatile("cp.async.cg.shared.global [%0], [%1], 16;"
                 :: "r"(saddr), "l"(g));
}
__device__ __forceinline__ void cp_commit(){
    asm volatile("cp.async.commit_group;" ::: "memory");
}
template<int N>
__device__ __forceinline__ void cp_wait(){
    asm volatile("cp.async.wait_group %0;" :: "n"(N) : "memory");
}
__device__ __forceinline__ void ldsm4(uint32_t addr, uint32_t* r){
    asm volatile("ldmatrix.sync.aligned.m8n8.x4.shared.b16 {%0,%1,%2,%3}, [%4];"
                 : "=r"(r[0]), "=r"(r[1]), "=r"(r[2]), "=r"(r[3]) : "r"(addr));
}
__device__ __forceinline__ void ldsm4t(uint32_t addr, uint32_t* r){
    asm volatile("ldmatrix.sync.aligned.m8n8.x4.trans.shared.b16 {%0,%1,%2,%3}, [%4];"
                 : "=r"(r[0]), "=r"(r[1]), "=r"(r[2]), "=r"(r[3]) : "r"(addr));
}
__device__ __forceinline__ void mma16816(float* c, const uint32_t* a, const uint32_t* b){
    asm volatile(
        "mma.sync.aligned.m16n8k16.row.col.f32.bf16.bf16.f32 "
        "{%0,%1,%2,%3}, {%4,%5,%6,%7}, {%8,%9}, {%0,%1,%2,%3};"
        : "+f"(c[0]), "+f"(c[1]), "+f"(c[2]), "+f"(c[3])
        : "r"(a[0]), "r"(a[1]), "r"(a[2]), "r"(a[3]), "r"(b[0]), "r"(b[1]));
}
__device__ __forceinline__ void mma16816h(float* c, const uint32_t* a, const uint32_t* b){
    asm volatile(
        "mma.sync.aligned.m16n8k16.row.col.f32.f16.f16.f32 "
        "{%0,%1,%2,%3}, {%4,%5,%6,%7}, {%8,%9}, {%0,%1,%2,%3};"
        : "+f"(c[0]), "+f"(c[1]), "+f"(c[2]), "+f"(c[3])
        : "r"(a[0]), "r"(a[1]), "r"(a[2]), "r"(a[3]), "r"(b[0]), "r"(b[1]));
}

// ---------------------------------------------------------------------------
// Tensor GEMM, cp.async double-buffered.
// MODE 0 (GEMM1): A = fp16 hi/lo (weights), B = single fp16 (x). 2 MMAs:
//                 (ah + al) * b.  Epilogue: bm==0 -> q bf16 hi/lo;
//                 bm==128 -> exp(k) fp16; bm==256 -> v fp16.
// MODE 1 (GEMM2): A = bf16 hi/lo (W2), B = bf16 hi/lo (q). 3 MMAs.
//                 Epilogue: fp32 + bias.
// ---------------------------------------------------------------------------
#define PA 80
#define PB 272
#define A_BUF_STRIDE (2 * 128 * PA)
#define B_BASE       (2 * A_BUF_STRIDE)
#define SMEM_G1 (B_BASE + 2 * (32 * PB))        // 58368
#define SMEM_G2 (B_BASE + 2 * (2 * 32 * PB))    // 75776

template<int K, int MODE>
__global__ __launch_bounds__(256, 2)
void tmma(const uint16_t* __restrict__ Ahg, const uint16_t* __restrict__ Alg,
          const uint16_t* __restrict__ Bhg, const uint16_t* __restrict__ Blg,
          float* __restrict__ Cout,
          __nv_bfloat16* __restrict__ Qh, __nv_bfloat16* __restrict__ Ql,
          __half* __restrict__ Kb, __half* __restrict__ Vb,
          const float* __restrict__ bias,
          long sA, long sB, long sC)
{
    extern __shared__ __align__(16) unsigned char sm[];
    __shared__ float sbias[128];

    const int BSTR = (MODE == 0) ? (32 * PB) : (2 * 32 * PB);

    const uint32_t smb = smem_u32(sm);
    const int tid = threadIdx.x;
    const int wid = tid >> 5;
    const int lid = tid & 31;
    const int bn = blockIdx.x * 128;
    const int bm = blockIdx.y * 128;
    const int bz = blockIdx.z;

    const int m0 = (wid >> 1) * 32;
    const int n0 = (wid & 1) * 64;

    const uint16_t* Abh = Ahg + (long)bz * sA;
    const uint16_t* Abl = Alg + (long)bz * sA;
    const uint16_t* Bbh = Bhg + (long)bz * sB;
    const uint16_t* Bbl = (MODE == 1) ? (Blg + (long)bz * sB) : nullptr;

    if (MODE == 1 && tid < 128) sbias[tid] = bias[bm + tid];

    const int rA = tid >> 2, cA = tid & 3;
    const int rB = tid >> 4, cB = tid & 15;

    const int a_lane = (m0 + (lid & 7) + ((lid >> 3) & 1) * 8) * PA + ((lid >> 4) & 1) * 16;
    const int b_lane = ((lid & 7) + ((lid >> 3) & 1) * 8) * PB + (n0 + ((lid >> 4) & 1) * 8) * 2;

    float acc[2][8][4];
#pragma unroll
    for (int i = 0; i < 2; i++)
#pragma unroll
        for (int j = 0; j < 8; j++)
#pragma unroll
            for (int q = 0; q < 4; q++) acc[i][j][q] = 0.f;

    const int nt = K / 32;

    auto issue = [&](int t, int buf) {
        const uint32_t ab = smb + buf * A_BUF_STRIDE;
        const uint32_t bb = smb + B_BASE + buf * BSTR;
        const int kt = t * 32;
#pragma unroll
        for (int w = 0; w < 2; w++) {
            int r = rA + w * 64;
            cp16(ab + r * PA + cA * 16,            &Abh[(long)(bm + r) * K + kt + cA * 8]);
            cp16(ab + 128 * PA + r * PA + cA * 16, &Abl[(long)(bm + r) * K + kt + cA * 8]);
        }
#pragma unroll
        for (int w = 0; w < 2; w++) {
            int r = rB + w * 16;
            cp16(bb + r * PB + cB * 16, &Bbh[(long)(kt + r) * L_ + bn + cB * 8]);
            if (MODE == 1)
                cp16(bb + 32 * PB + r * PB + cB * 16,
                     &Bbl[(long)(kt + r) * L_ + bn + cB * 8]);
        }
        cp_commit();
    };

    issue(0, 0);
    if (nt > 1) issue(1, 1);

    for (int t = 0; t < nt; t++) {
        const int cur = t & 1;
        if (t + 1 < nt) cp_wait<1>(); else cp_wait<0>();
        __syncthreads();

        {
            const uint32_t a_hi = smb + cur * A_BUF_STRIDE;
            const uint32_t a_lo = a_hi + 128 * PA;
            const uint32_t b_hi = smb + B_BASE + cur * BSTR;
            const uint32_t b_lo = b_hi + 32 * PB;   // MODE 1 only
#pragma unroll
            for (int kk = 0; kk < 2; kk++) {
                uint32_t ah[2][4], alr[2][4];
                ldsm4(a_hi + a_lane + kk * 32,           ah[0]);
                ldsm4(a_hi + a_lane + kk * 32 + 16 * PA, ah[1]);
                ldsm4(a_lo + a_lane + kk * 32,           alr[0]);
                ldsm4(a_lo + a_lane + kk * 32 + 16 * PA, alr[1]);
#pragma unroll
                for (int half = 0; half < 2; half++) {
                    uint32_t bh[2][4];
                    ldsm4t(b_hi + b_lane + kk * 16 * PB + (half * 2)     * 32, bh[0]);
                    ldsm4t(b_hi + b_lane + kk * 16 * PB + (half * 2 + 1) * 32, bh[1]);
                    if (MODE == 0) {
#pragma unroll
                        for (int mi = 0; mi < 2; mi++)
#pragma unroll
                            for (int jj = 0; jj < 4; jj++) {
                                int ni = half * 4 + jj;
                                const uint32_t* bp = &bh[jj >> 1][(jj & 1) * 2];
                                mma16816h(acc[mi][ni], ah[mi],  bp);
                                mma16816h(acc[mi][ni], alr[mi], bp);
                            }
                    } else {
                        uint32_t blr[2][4];
                        ldsm4t(b_lo + b_lane + kk * 16 * PB + (half * 2)     * 32, blr[0]);
                        ldsm4t(b_lo + b_lane + kk * 16 * PB + (half * 2 + 1) * 32, blr[1]);
#pragma unroll
                        for (int mi = 0; mi < 2; mi++)
#pragma unroll
                            for (int jj = 0; jj < 4; jj++) {
                                int ni = half * 4 + jj;
                                const uint32_t* bhp = &bh[jj >> 1][(jj & 1) * 2];
                                const uint32_t* blp = &blr[jj >> 1][(jj & 1) * 2];
                                mma16816(acc[mi][ni], ah[mi],  bhp);
                                mma16816(acc[mi][ni], ah[mi],  blp);
                                mma16816(acc[mi][ni], alr[mi], bhp);
                            }
                    }
                }
            }
        }

        if (t + 2 < nt) {
            __syncthreads();
            issue(t + 2, cur);
        }
    }

    if (MODE == 0 && bm == 0) {
        __nv_bfloat16* qh = Qh + (long)bz * HID * L_;
        __nv_bfloat16* ql = Ql + (long)bz * HID * L_;
#pragma unroll
        for (int mi = 0; mi < 2; mi++) {
            int r0 = m0 + mi * 16 + (lid >> 2);
            int r1 = r0 + 8;
#pragma unroll
            for (int ni = 0; ni < 8; ni++) {
                int col = bn + n0 + ni * 8 + (lid & 3) * 2;
#pragma unroll
                for (int rr = 0; rr < 2; rr++) {
                    int r = rr ? r1 : r0;
                    float vx = acc[mi][ni][rr * 2], vy = acc[mi][ni][rr * 2 + 1];
                    __nv_bfloat16 hx = __float2bfloat16_rn(vx);
                    __nv_bfloat16 hy = __float2bfloat16_rn(vy);
                    *(__nv_bfloat162*)&qh[(long)r * L_ + col] = __nv_bfloat162(hx, hy);
                    *(__nv_bfloat162*)&ql[(long)r * L_ + col] = __nv_bfloat162(
                        __float2bfloat16_rn(vx - __bfloat162float(hx)),
                        __float2bfloat16_rn(vy - __bfloat162float(hy)));
                }
            }
        }
    } else if (MODE == 0) {
        // k rows -> exp(k) fp16 ; v rows -> v fp16
        const bool is_k = (bm == 128);
        __half* dst = (is_k ? Kb : Vb) + (long)bz * HID * L_;
#pragma unroll
        for (int mi = 0; mi < 2; mi++) {
            int lr0 = m0 + mi * 16 + (lid >> 2);
            int lr1 = lr0 + 8;
#pragma unroll
            for (int ni = 0; ni < 8; ni++) {
                int col = bn + n0 + ni * 8 + (lid & 3) * 2;
#pragma unroll
                for (int rr = 0; rr < 2; rr++) {
                    int lr = rr ? lr1 : lr0;
                    float vx = acc[mi][ni][rr * 2], vy = acc[mi][ni][rr * 2 + 1];
                    if (is_k) { vx = __expf(vx); vy = __expf(vy); }
                    *(__half2*)&dst[(long)lr * L_ + col] = __floats2half2_rn(vx, vy);
                }
            }
        }
    } else {
        float* Cb = Cout + (long)bz * sC;
#pragma unroll
        for (int mi = 0; mi < 2; mi++) {
            int r0 = bm + m0 + mi * 16 + (lid >> 2);
            int r1 = r0 + 8;
            float bv0 = sbias[r0 - bm];
            float bv1 = sbias[r1 - bm];
#pragma unroll
            for (int ni = 0; ni < 8; ni++) {
                int col = bn + n0 + ni * 8 + (lid & 3) * 2;
                float2 v0 = make_float2(acc[mi][ni][0] + bv0, acc[mi][ni][1] + bv0);
                float2 v1 = make_float2(acc[mi][ni][2] + bv1, acc[mi][ni][3] + bv1);
                *(float2*)&Cb[(long)r0 * L_ + col] = v0;
                *(float2*)&Cb[(long)r1 * L_ + col] = v1;
            }
        }
    }
}

// ---------------------------------------------------------------------------
// Split fp32 array -> fp16 hi/lo (weights)
// ---------------------------------------------------------------------------
__global__ __launch_bounds__(256)
void split_w16(const float* __restrict__ src,
               __half* __restrict__ hi, __half* __restrict__ lo)
{
    long i = ((long)blockIdx.x * 256 + threadIdx.x) * 8;
    float4 v0 = *(const float4*)&src[i];
    float4 v1 = *(const float4*)&src[i + 4];
    __half h[8], l[8];
    float f[8] = {v0.x, v0.y, v0.z, v0.w, v1.x, v1.y, v1.z, v1.w};
#pragma unroll
    for (int j = 0; j < 8; j++) {
        h[j] = __float2half_rn(f[j]);
        l[j] = __float2half_rn(f[j] - __half2float(h[j]));
    }
    *(uint4*)&hi[i] = *(uint4*)h;
    *(uint4*)&lo[i] = *(uint4*)l;
}

// ---------------------------------------------------------------------------
// Convert fp32 x -> single fp16
// ---------------------------------------------------------------------------
__global__ __launch_bounds__(256)
void conv_x16(const float* __restrict__ src, __half* __restrict__ dst)
{
    long i = ((long)blockIdx.x * 256 + threadIdx.x) * 8;
    float4 v0 = *(const float4*)&src[i];
    float4 v1 = *(const float4*)&src[i + 4];
    __half h[8];
    h[0] = __float2half_rn(v0.x); h[1] = __float2half_rn(v0.y);
    h[2] = __float2half_rn(v0.z); h[3] = __float2half_rn(v0.w);
    h[4] = __float2half_rn(v1.x); h[5] = __float2half_rn(v1.y);
    h[6] = __float2half_rn(v1.z); h[7] = __float2half_rn(v1.w);
    *(uint4*)&dst[i] = *(uint4*)h;
}

// ---------------------------------------------------------------------------
// Context kernel: tensor-core mma over fp16 Ek/V, cp.async 3-stage (R15).
// ---------------------------------------------------------------------------
#define CST 3
#define EPITCH 72

__global__ __launch_bounds__(128)
void ctx_kernel()
{
    const int chunk = blockIdx.x;
    const int h     = blockIdx.y;
    const int b     = blockIdx.z;

    __shared__ __half Eks[CST][32][EPITCH];
    __shared__ __half Vss[CST][32][EPITCH];
    __shared__ float rnum[4][32][32];
    __shared__ float rden[32];

    const int tid = threadIdx.x;
    const int w   = tid >> 5;
    const int l   = tid & 31;

    const __half* kb = g_kb + ((long)b * HID + h * 32) * L_;
    const __half* vb = g_vb + ((long)b * HID + h * 32) * L_;
    const int lbase = chunk * CHL;

    const uint32_t ebase = smem_u32(&Eks[0][0][0]);
    const uint32_t vbase = smem_u32(&Vss[0][0][0]);
    const uint32_t stage_bytes = 32 * EPITCH * 2;

    auto issue = [&](int t) {
        const int s = t % CST;
        const int l0 = lbase + t * 64;
#pragma unroll
        for (int i = 0; i < 2; i++) {
            int idx = tid + i * 128;
            int r = idx >> 3, c = idx & 7;
            cp16(ebase + s * stage_bytes + r * (EPITCH * 2) + c * 16,
                 &kb[(long)r * L_ + l0 + c * 8]);
            cp16(vbase + s * stage_bytes + r * (EPITCH * 2) + c * 16,
                 &vb[(long)r * L_ + l0 + c * 8]);
        }
        cp_commit();
    };

    float acc[2][4][4];
#pragma unroll
    for (int mi = 0; mi < 2; mi++)
#pragma unroll
        for (int ni = 0; ni < 4; ni++)
#pragma unroll
            for (int q = 0; q < 4; q++) acc[mi][ni][q] = 0.f;
    float dacc = 0.f;

    issue(0); issue(1); issue(2);

    const int a_off0 = ((l & 7) + ((l >> 3) & 1) * 8) * (EPITCH * 2) + ((l >> 4) & 1) * 16 + w * 32;
    const int b_off0 = ((l >> 4) * 8 + (l & 7)) * (EPITCH * 2) + ((l >> 3) & 1) * 16 + w * 32;

#pragma unroll
    for (int t = 0; t < CT; t++) {
        if (t + 2 < CT)      cp_wait<2>();
        else if (t + 1 < CT) cp_wait<1>();
        else                 cp_wait<0>();
        __syncthreads();

        const int s = t % CST;
        const uint32_t eS = ebase + s * stage_bytes;
        const uint32_t vS = vbase + s * stage_bytes;

        {
            const int d = tid >> 2, q = tid & 3;
            const uint32_t* p = (const uint32_t*)&Eks[s][d][q * 16];
#pragma unroll
            for (int j = 0; j < 8; j++) {
                float2 f = __half22float2(*(const __half2*)&p[j]);
                dacc += f.x + f.y;
            }
        }

        uint32_t aa[2][4], bb[2][4];
        ldsm4(eS + a_off0,                      aa[0]);
        ldsm4(eS + a_off0 + 16 * (EPITCH * 2),  aa[1]);
        ldsm4(vS + b_off0,                      bb[0]);
        ldsm4(vS + b_off0 + 16 * (EPITCH * 2),  bb[1]);
#pragma unroll
        for (int mi = 0; mi < 2; mi++)
#pragma unroll
            for (int ni = 0; ni < 4; ni++)
                mma16816h(acc[mi][ni], aa[mi], &bb[ni >> 1][(ni & 1) * 2]);

        __syncthreads();
        if (t + 3 < CT) issue(t + 3);
    }

    __syncthreads();
#pragma unroll
    for (int mi = 0; mi < 2; mi++) {
        int r0 = mi * 16 + (l >> 2);
        int r1 = r0 + 8;
#pragma unroll
        for (int ni = 0; ni < 4; ni++) {
            int c = ni * 8 + (l & 3) * 2;
            rnum[w][r0][c]     = acc[mi][ni][0];
            rnum[w][r0][c + 1] = acc[mi][ni][1];
            rnum[w][r1][c]     = acc[mi][ni][2];
            rnum[w][r1][c + 1] = acc[mi][ni][3];
        }
    }
    dacc += __shfl_xor_sync(0xFFFFFFFF, dacc, 1);
    dacc += __shfl_xor_sync(0xFFFFFFFF, dacc, 2);
    if ((l & 3) == 0) rden[w * 8 + (l >> 2)] = dacc;
    __syncthreads();

    const long pset = ((long)b * H_ + h) * NCH + chunk;
#pragma unroll
    for (int j = 0; j < 8; j++) {
        int idx = tid + j * 128;
        int d = idx >> 5, e = idx & 31;
        float s = rnum[0][d][e] + rnum[1][d][e] + rnum[2][d][e] + rnum[3][d][e];
        g_pn[(pset * 32 + d) * 32 + e] = s;
    }
    if (tid < 32) g_pd[pset * 32 + tid] = rden[tid];
}

// ---------------------------------------------------------------------------
// Normalize context: reduce NCH chunk partials, divide -> g_ctx[b][h][d][e]
// ---------------------------------------------------------------------------
__global__ __launch_bounds__(256)
void ctx_norm()
{
    const int h = blockIdx.x, b = blockIdx.y;
    const int tid = threadIdx.x;
    const int d = tid >> 3, e0 = (tid & 7) * 4;
    float num[4] = {0.f, 0.f, 0.f, 0.f};
    float den = 0.f;
#pragma unroll
    for (int c = 0; c < NCH; c++) {
        long pset = ((long)b * H_ + h) * NCH + c;
        const float4 p = *(const float4*)&g_pn[(pset * 32 + d) * 32 + e0];
        num[0] += p.x; num[1] += p.y; num[2] += p.z; num[3] += p.w;
        den += g_pd[pset * 32 + d];
    }
    float inv = 1.f / den;
    float4 o = make_float4(num[0] * inv, num[1] * inv, num[2] * inv, num[3] * inv);
    *(float4*)&g_ctx[(((long)b * H_ + h) * 32 + d) * 32 + e0] = o;
}

// ---------------------------------------------------------------------------
// W2 = w_out @ T_b  (block-diagonal), bf16 hi/lo out.
// ---------------------------------------------------------------------------
__global__ __launch_bounds__(256)
void w2g(const float* __restrict__ w_out)
{
    const int ot = blockIdx.x, b = blockIdx.y;
    __shared__ float ctxs[H_ * 32 * 32];
    __shared__ float wsm[16][128];
    const int tid = threadIdx.x;

#pragma unroll
    for (int i = 0; i < 4; i++) {
        int idx = (tid + i * 256) * 4;
        *(float4*)&ctxs[idx] = *(const float4*)&g_ctx[(long)b * H_ * 1024 + idx];
    }
#pragma unroll
    for (int i = 0; i < 2; i++) {
        int idx = tid + i * 256;
        int oo = idx >> 5, c4 = idx & 31;
        *(float4*)&wsm[oo][c4 * 4] =
            *(const float4*)&w_out[((long)(ot * 16 + oo)) * HID + c4 * 4];
    }
    __syncthreads();

#pragma unroll
    for (int j = 0; j < 8; j++) {
        int idx = tid + j * 256;
        int oo = idx >> 7, hd = idx & 127;
        int h = hd >> 5, d = hd & 31;
        const float* cr = &ctxs[(h * 32 + d) * 32];
        const float* wr = &wsm[oo][h * 32];
        float s = 0.f;
#pragma unroll
        for (int e = 0; e < 32; e++) s += wr[e] * cr[e];
        long oidx = (((long)b * C_) + ot * 16 + oo) * HID + hd;
        __nv_bfloat16 hh = __float2bfloat16_rn(s);
        g_W2h[oidx] = hh;
        g_W2l[oidx] = __float2bfloat16_rn(s - __bfloat162float(hh));
    }
}

// ---------------------------------------------------------------------------
extern "C" void kernel_launch(void* const* d_in, const int* in_sizes, int n_in,
                              void* d_out, int out_size)
{
    const float* x     = (const float*)d_in[0];
    const float* w_qkv = (const float*)d_in[1];
    const float* w_out = (const float*)d_in[2];
    const float* b_out = (const float*)d_in[3];
    float* out = (float*)d_out;

    __half *wh16, *wl16, *xf, *kb, *vb;
    __nv_bfloat16 *qh, *ql, *W2h, *W2l;
    cudaGetSymbolAddress((void**)&wh16, g_wh16);
    cudaGetSymbolAddress((void**)&wl16, g_wl16);
    cudaGetSymbolAddress((void**)&xf,   g_xf);
    cudaGetSymbolAddress((void**)&qh,   g_qh);
    cudaGetSymbolAddress((void**)&ql,   g_ql);
    cudaGetSymbolAddress((void**)&kb,   g_kb);
    cudaGetSymbolAddress((void**)&vb,   g_vb);
    cudaGetSymbolAddress((void**)&W2h,  g_W2h);
    cudaGetSymbolAddress((void**)&W2l,  g_W2l);

    cudaFuncSetAttribute(tmma<512, 0>,
                         cudaFuncAttributeMaxDynamicSharedMemorySize, SMEM_G1);
    cudaFuncSetAttribute(tmma<128, 1>,
                         cudaFuncAttributeMaxDynamicSharedMemorySize, SMEM_G2);

    // 0) weight split (fp16 hi/lo) + x -> fp16
    split_w16<<<(O3 * C_) / 2048, 256>>>(w_qkv, wh16, wl16);
    conv_x16<<<(int)(((long)B_ * C_ * L_) / 2048), 256>>>(x, xf);

    // 1) qkv: q -> bf16 hi/lo, k -> exp(k) fp16, v -> fp16
    {
        dim3 grid(L_ / 128, O3 / 128, B_);
        tmma<512, 0><<<grid, 256, SMEM_G1>>>(
            (const uint16_t*)wh16, (const uint16_t*)wl16,
            (const uint16_t*)xf, nullptr,
            nullptr, qh, ql, kb, vb, nullptr,
            0L, (long)C_ * L_, 0L);
    }
    // 2) context partials (tensor-core fp16, pipelined streaming)
    {
        dim3 grid(NCH, H_, B_);
        ctx_kernel<<<grid, 128>>>();
    }
    // 3) normalize + fold
    {
        dim3 g1(H_, B_);
        ctx_norm<<<g1, 256>>>();
        dim3 g2(32, B_);
        w2g<<<g2, 256>>>(w_out);
    }
    // 4) out = W2_b @ q_b + b_out  (bf16 3-split, unchanged)
    {
        dim3 grid(L_ / 128, C_ / 128, B_);
        tmma<128, 1><<<grid, 256, SMEM_G2>>>(
            (const uint16_t*)W2h, (const uint16_t*)W2l,
            (const uint16_t*)qh, (const uint16_t*)ql,
            out, nullptr, nullptr, nullptr, nullptr, b_out,
            (long)C_ * HID, (long)HID * L_, (long)C_ * L_);
    }
}

// round 17
// speedup vs baseline: 1.6168x; 1.6168x over previous
#include <cuda_runtime.h>
#include <cuda_bf16.h>
#include <cuda_fp16.h>
#include <math.h>
#include <stdint.h>

#define B_  8
#define C_  512
#define L_  8192
#define H_  4
#define HID 128
#define O3  384   // rows in w_qkv: [0,128)=q, [128,256)=k, [256,384)=v
#define NCH 32    // ctx column chunks
#define CHL (L_ / NCH)     // 256 columns per chunk
#define CT  (CHL / 64)     // 4 tiles of 64 cols per chunk

// Scratch (static device arrays — no runtime allocation)
__device__ float g_pn [(size_t)B_ * H_ * NCH * 32 * 32];
__device__ float g_pd [(size_t)B_ * H_ * NCH * 32];
__device__ float g_ctx[(size_t)B_ * H_ * 32 * 32];
__device__ __half g_wh16[(size_t)O3 * C_];       // w_qkv hi (fp16)
__device__ __half g_wl16[(size_t)O3 * C_];       // w_qkv lo (fp16)
__device__ __half g_xf [(size_t)B_ * C_ * L_];   // x fp16
__device__ __half g_qf [(size_t)B_ * HID * L_];  // q fp16
__device__ __half g_kb [(size_t)B_ * HID * L_];  // exp(k) fp16
__device__ __half g_vb [(size_t)B_ * HID * L_];  // v fp16
__device__ __half g_W2h[(size_t)B_ * C_ * HID];  // W2 hi (fp16)
__device__ __half g_W2l[(size_t)B_ * C_ * HID];  // W2 lo (fp16)

// ---------------------------- helpers --------------------------------------
__device__ __forceinline__ uint32_t smem_u32(const void* p){
    uint32_t a;
    asm("{ .reg .u64 t; cvta.to.shared.u64 t, %1; cvt.u32.u64 %0, t; }"
        : "=r"(a) : "l"(p));
    return a;
}
__device__ __forceinline__ void cp16(uint32_t saddr, const void* g){
    asm volatile("cp.async.cg.shared.global [%0], [%1], 16;"
                 :: "r"(saddr), "l"(g));
}
__device__ __forceinline__ void cp_commit(){
    asm volatile("cp.async.commit_group;" ::: "memory");
}
template<int N>
__device__ __forceinline__ void cp_wait(){
    asm volatile("cp.async.wait_group %0;" :: "n"(N) : "memory");
}
__device__ __forceinline__ void ldsm4(uint32_t addr, uint32_t* r){
    asm volatile("ldmatrix.sync.aligned.m8n8.x4.shared.b16 {%0,%1,%2,%3}, [%4];"
                 : "=r"(r[0]), "=r"(r[1]), "=r"(r[2]), "=r"(r[3]) : "r"(addr));
}
__device__ __forceinline__ void ldsm4t(uint32_t addr, uint32_t* r){
    asm volatile("ldmatrix.sync.aligned.m8n8.x4.trans.shared.b16 {%0,%1,%2,%3}, [%4];"
                 : "=r"(r[0]), "=r"(r[1]), "=r"(r[2]), "=r"(r[3]) : "r"(addr));
}
__device__ __forceinline__ void mma16816h(float* c, const uint32_t* a, const uint32_t* b){
    asm volatile(
        "mma.sync.aligned.m16n8k16.row.col.f32.f16.f16.f32 "
        "{%0,%1,%2,%3}, {%4,%5,%6,%7}, {%8,%9}, {%0,%1,%2,%3};"
        : "+f"(c[0]), "+f"(c[1]), "+f"(c[2]), "+f"(c[3])
        : "r"(a[0]), "r"(a[1]), "r"(a[2]), "r"(a[3]), "r"(b[0]), "r"(b[1]));
}

// ---------------------------------------------------------------------------
// Unified tensor GEMM: A = fp16 hi/lo (22-bit weights), B = single fp16.
// D = (ah + al) * b, fp32 accum, 2 MMAs per frag. cp.async double-buffered.
// MODE 0 (GEMM1, K=512): bm==0 -> q fp16; bm==128 -> exp(k) fp16;
//                        bm==256 -> v fp16.
// MODE 1 (GEMM2, K=128): fp32 + bias to Cout.
// ---------------------------------------------------------------------------
#define PA 80
#define PB 272
#define A_BUF_STRIDE (2 * 128 * PA)
#define B_BASE       (2 * A_BUF_STRIDE)
#define B_BUF_STRIDE (32 * PB)
#define SMEM_TOT (B_BASE + 2 * B_BUF_STRIDE)   // 58368

template<int K, int MODE>
__global__ __launch_bounds__(256, 2)
void tmma(const uint16_t* __restrict__ Ahg, const uint16_t* __restrict__ Alg,
          const uint16_t* __restrict__ Bhg,
          float* __restrict__ Cout,
          __half* __restrict__ Qf, __half* __restrict__ Kb, __half* __restrict__ Vb,
          const float* __restrict__ bias,
          long sA, long sB, long sC)
{
    extern __shared__ __align__(16) unsigned char sm[];
    __shared__ float sbias[128];

    const uint32_t smb = smem_u32(sm);
    const int tid = threadIdx.x;
    const int wid = tid >> 5;
    const int lid = tid & 31;
    const int bn = blockIdx.x * 128;
    const int bm = blockIdx.y * 128;
    const int bz = blockIdx.z;

    const int m0 = (wid >> 1) * 32;
    const int n0 = (wid & 1) * 64;

    const uint16_t* Abh = Ahg + (long)bz * sA;
    const uint16_t* Abl = Alg + (long)bz * sA;
    const uint16_t* Bbh = Bhg + (long)bz * sB;

    if (MODE == 1 && tid < 128) sbias[tid] = bias[bm + tid];

    const int rA = tid >> 2, cA = tid & 3;
    const int rB = tid >> 4, cB = tid & 15;

    const int a_lane = (m0 + (lid & 7) + ((lid >> 3) & 1) * 8) * PA + ((lid >> 4) & 1) * 16;
    const int b_lane = ((lid & 7) + ((lid >> 3) & 1) * 8) * PB + (n0 + ((lid >> 4) & 1) * 8) * 2;

    float acc[2][8][4];
#pragma unroll
    for (int i = 0; i < 2; i++)
#pragma unroll
        for (int j = 0; j < 8; j++)
#pragma unroll
            for (int q = 0; q < 4; q++) acc[i][j][q] = 0.f;

    const int nt = K / 32;

    auto issue = [&](int t, int buf) {
        const uint32_t ab = smb + buf * A_BUF_STRIDE;
        const uint32_t bb = smb + B_BASE + buf * B_BUF_STRIDE;
        const int kt = t * 32;
#pragma unroll
        for (int w = 0; w < 2; w++) {
            int r = rA + w * 64;
            cp16(ab + r * PA + cA * 16,            &Abh[(long)(bm + r) * K + kt + cA * 8]);
            cp16(ab + 128 * PA + r * PA + cA * 16, &Abl[(long)(bm + r) * K + kt + cA * 8]);
        }
#pragma unroll
        for (int w = 0; w < 2; w++) {
            int r = rB + w * 16;
            cp16(bb + r * PB + cB * 16, &Bbh[(long)(kt + r) * L_ + bn + cB * 8]);
        }
        cp_commit();
    };

    issue(0, 0);
    if (nt > 1) issue(1, 1);

    for (int t = 0; t < nt; t++) {
        const int cur = t & 1;
        if (t + 1 < nt) cp_wait<1>(); else cp_wait<0>();
        __syncthreads();

        {
            const uint32_t a_hi = smb + cur * A_BUF_STRIDE;
            const uint32_t a_lo = a_hi + 128 * PA;
            const uint32_t b_hi = smb + B_BASE + cur * B_BUF_STRIDE;
#pragma unroll
            for (int kk = 0; kk < 2; kk++) {
                uint32_t ah[2][4], alr[2][4];
                ldsm4(a_hi + a_lane + kk * 32,           ah[0]);
                ldsm4(a_hi + a_lane + kk * 32 + 16 * PA, ah[1]);
                ldsm4(a_lo + a_lane + kk * 32,           alr[0]);
                ldsm4(a_lo + a_lane + kk * 32 + 16 * PA, alr[1]);
#pragma unroll
                for (int half = 0; half < 2; half++) {
                    uint32_t bh[2][4];
                    ldsm4t(b_hi + b_lane + kk * 16 * PB + (half * 2)     * 32, bh[0]);
                    ldsm4t(b_hi + b_lane + kk * 16 * PB + (half * 2 + 1) * 32, bh[1]);
#pragma unroll
                    for (int mi = 0; mi < 2; mi++)
#pragma unroll
                        for (int jj = 0; jj < 4; jj++) {
                            int ni = half * 4 + jj;
                            const uint32_t* bp = &bh[jj >> 1][(jj & 1) * 2];
                            mma16816h(acc[mi][ni], ah[mi],  bp);
                            mma16816h(acc[mi][ni], alr[mi], bp);
                        }
                }
            }
        }

        if (t + 2 < nt) {
            __syncthreads();
            issue(t + 2, cur);
        }
    }

    if (MODE == 0) {
        // q / exp(k) / v all stored as single fp16
        const bool is_k = (bm == 128);
        __half* dst = (bm == 0 ? Qf : (is_k ? Kb : Vb)) + (long)bz * HID * L_;
#pragma unroll
        for (int mi = 0; mi < 2; mi++) {
            int lr0 = m0 + mi * 16 + (lid >> 2);   // local row 0..127
            int lr1 = lr0 + 8;
#pragma unroll
            for (int ni = 0; ni < 8; ni++) {
                int col = bn + n0 + ni * 8 + (lid & 3) * 2;
#pragma unroll
                for (int rr = 0; rr < 2; rr++) {
                    int lr = rr ? lr1 : lr0;
                    float vx = acc[mi][ni][rr * 2], vy = acc[mi][ni][rr * 2 + 1];
                    if (is_k) { vx = __expf(vx); vy = __expf(vy); }
                    *(__half2*)&dst[(long)lr * L_ + col] = __floats2half2_rn(vx, vy);
                }
            }
        }
    } else {
        float* Cb = Cout + (long)bz * sC;
#pragma unroll
        for (int mi = 0; mi < 2; mi++) {
            int r0 = bm + m0 + mi * 16 + (lid >> 2);
            int r1 = r0 + 8;
            float bv0 = sbias[r0 - bm];
            float bv1 = sbias[r1 - bm];
#pragma unroll
            for (int ni = 0; ni < 8; ni++) {
                int col = bn + n0 + ni * 8 + (lid & 3) * 2;
                float2 v0 = make_float2(acc[mi][ni][0] + bv0, acc[mi][ni][1] + bv0);
                float2 v1 = make_float2(acc[mi][ni][2] + bv1, acc[mi][ni][3] + bv1);
                *(float2*)&Cb[(long)r0 * L_ + col] = v0;
                *(float2*)&Cb[(long)r1 * L_ + col] = v1;
            }
        }
    }
}

// ---------------------------------------------------------------------------
// Split fp32 -> fp16 hi/lo (weights)
// ---------------------------------------------------------------------------
__global__ __launch_bounds__(256)
void split_w16(const float* __restrict__ src,
               __half* __restrict__ hi, __half* __restrict__ lo)
{
    long i = ((long)blockIdx.x * 256 + threadIdx.x) * 8;
    float4 v0 = *(const float4*)&src[i];
    float4 v1 = *(const float4*)&src[i + 4];
    __half h[8], l[8];
    float f[8] = {v0.x, v0.y, v0.z, v0.w, v1.x, v1.y, v1.z, v1.w};
#pragma unroll
    for (int j = 0; j < 8; j++) {
        h[j] = __float2half_rn(f[j]);
        l[j] = __float2half_rn(f[j] - __half2float(h[j]));
    }
    *(uint4*)&hi[i] = *(uint4*)h;
    *(uint4*)&lo[i] = *(uint4*)l;
}

// ---------------------------------------------------------------------------
// Convert fp32 x -> single fp16
// ---------------------------------------------------------------------------
__global__ __launch_bounds__(256)
void conv_x16(const float* __restrict__ src, __half* __restrict__ dst)
{
    long i = ((long)blockIdx.x * 256 + threadIdx.x) * 8;
    float4 v0 = *(const float4*)&src[i];
    float4 v1 = *(const float4*)&src[i + 4];
    __half h[8];
    h[0] = __float2half_rn(v0.x); h[1] = __float2half_rn(v0.y);
    h[2] = __float2half_rn(v0.z); h[3] = __float2half_rn(v0.w);
    h[4] = __float2half_rn(v1.x); h[5] = __float2half_rn(v1.y);
    h[6] = __float2half_rn(v1.z); h[7] = __float2half_rn(v1.w);
    *(uint4*)&dst[i] = *(uint4*)h;
}

// ---------------------------------------------------------------------------
// Context kernel: tensor-core mma over fp16 Ek/V, cp.async 3-stage (R15).
// ---------------------------------------------------------------------------
#define CST 3
#define EPITCH 72

__global__ __launch_bounds__(128)
void ctx_kernel()
{
    const int chunk = blockIdx.x;
    const int h     = blockIdx.y;
    const int b     = blockIdx.z;

    __shared__ __half Eks[CST][32][EPITCH];
    __shared__ __half Vss[CST][32][EPITCH];
    __shared__ float rnum[4][32][32];
    __shared__ float rden[32];

    const int tid = threadIdx.x;
    const int w   = tid >> 5;
    const int l   = tid & 31;

    const __half* kb = g_kb + ((long)b * HID + h * 32) * L_;
    const __half* vb = g_vb + ((long)b * HID + h * 32) * L_;
    const int lbase = chunk * CHL;

    const uint32_t ebase = smem_u32(&Eks[0][0][0]);
    const uint32_t vbase = smem_u32(&Vss[0][0][0]);
    const uint32_t stage_bytes = 32 * EPITCH * 2;

    auto issue = [&](int t) {
        const int s = t % CST;
        const int l0 = lbase + t * 64;
#pragma unroll
        for (int i = 0; i < 2; i++) {
            int idx = tid + i * 128;
            int r = idx >> 3, c = idx & 7;
            cp16(ebase + s * stage_bytes + r * (EPITCH * 2) + c * 16,
                 &kb[(long)r * L_ + l0 + c * 8]);
            cp16(vbase + s * stage_bytes + r * (EPITCH * 2) + c * 16,
                 &vb[(long)r * L_ + l0 + c * 8]);
        }
        cp_commit();
    };

    float acc[2][4][4];
#pragma unroll
    for (int mi = 0; mi < 2; mi++)
#pragma unroll
        for (int ni = 0; ni < 4; ni++)
#pragma unroll
            for (int q = 0; q < 4; q++) acc[mi][ni][q] = 0.f;
    float dacc = 0.f;

    issue(0); issue(1); issue(2);

    const int a_off0 = ((l & 7) + ((l >> 3) & 1) * 8) * (EPITCH * 2) + ((l >> 4) & 1) * 16 + w * 32;
    const int b_off0 = ((l >> 4) * 8 + (l & 7)) * (EPITCH * 2) + ((l >> 3) & 1) * 16 + w * 32;

#pragma unroll
    for (int t = 0; t < CT; t++) {
        if (t + 2 < CT)      cp_wait<2>();
        else if (t + 1 < CT) cp_wait<1>();
        else                 cp_wait<0>();
        __syncthreads();

        const int s = t % CST;
        const uint32_t eS = ebase + s * stage_bytes;
        const uint32_t vS = vbase + s * stage_bytes;

        {
            const int d = tid >> 2, q = tid & 3;
            const uint32_t* p = (const uint32_t*)&Eks[s][d][q * 16];
#pragma unroll
            for (int j = 0; j < 8; j++) {
                float2 f = __half22float2(*(const __half2*)&p[j]);
                dacc += f.x + f.y;
            }
        }

        uint32_t aa[2][4], bb[2][4];
        ldsm4(eS + a_off0,                      aa[0]);
        ldsm4(eS + a_off0 + 16 * (EPITCH * 2),  aa[1]);
        ldsm4(vS + b_off0,                      bb[0]);
        ldsm4(vS + b_off0 + 16 * (EPITCH * 2),  bb[1]);
#pragma unroll
        for (int mi = 0; mi < 2; mi++)
#pragma unroll
            for (int ni = 0; ni < 4; ni++)
                mma16816h(acc[mi][ni], aa[mi], &bb[ni >> 1][(ni & 1) * 2]);

        __syncthreads();
        if (t + 3 < CT) issue(t + 3);
    }

    __syncthreads();
#pragma unroll
    for (int mi = 0; mi < 2; mi++) {
        int r0 = mi * 16 + (l >> 2);
        int r1 = r0 + 8;
#pragma unroll
        for (int ni = 0; ni < 4; ni++) {
            int c = ni * 8 + (l & 3) * 2;
            rnum[w][r0][c]     = acc[mi][ni][0];
            rnum[w][r0][c + 1] = acc[mi][ni][1];
            rnum[w][r1][c]     = acc[mi][ni][2];
            rnum[w][r1][c + 1] = acc[mi][ni][3];
        }
    }
    dacc += __shfl_xor_sync(0xFFFFFFFF, dacc, 1);
    dacc += __shfl_xor_sync(0xFFFFFFFF, dacc, 2);
    if ((l & 3) == 0) rden[w * 8 + (l >> 2)] = dacc;
    __syncthreads();

    const long pset = ((long)b * H_ + h) * NCH + chunk;
#pragma unroll
    for (int j = 0; j < 8; j++) {
        int idx = tid + j * 128;
        int d = idx >> 5, e = idx & 31;
        float s = rnum[0][d][e] + rnum[1][d][e] + rnum[2][d][e] + rnum[3][d][e];
        g_pn[(pset * 32 + d) * 32 + e] = s;
    }
    if (tid < 32) g_pd[pset * 32 + tid] = rden[tid];
}

// ---------------------------------------------------------------------------
// Normalize context: reduce NCH chunk partials, divide -> g_ctx[b][h][d][e]
// ---------------------------------------------------------------------------
__global__ __launch_bounds__(256)
void ctx_norm()
{
    const int h = blockIdx.x, b = blockIdx.y;
    const int tid = threadIdx.x;
    const int d = tid >> 3, e0 = (tid & 7) * 4;
    float num[4] = {0.f, 0.f, 0.f, 0.f};
    float den = 0.f;
#pragma unroll
    for (int c = 0; c < NCH; c++) {
        long pset = ((long)b * H_ + h) * NCH + c;
        const float4 p = *(const float4*)&g_pn[(pset * 32 + d) * 32 + e0];
        num[0] += p.x; num[1] += p.y; num[2] += p.z; num[3] += p.w;
        den += g_pd[pset * 32 + d];
    }
    float inv = 1.f / den;
    float4 o = make_float4(num[0] * inv, num[1] * inv, num[2] * inv, num[3] * inv);
    *(float4*)&g_ctx[(((long)b * H_ + h) * 32 + d) * 32 + e0] = o;
}

// ---------------------------------------------------------------------------
// W2 = w_out @ T_b  (block-diagonal), fp16 hi/lo out.
// ---------------------------------------------------------------------------
__global__ __launch_bounds__(256)
void w2g(const float* __restrict__ w_out)
{
    const int ot = blockIdx.x, b = blockIdx.y;
    __shared__ float ctxs[H_ * 32 * 32];
    __shared__ float wsm[16][128];
    const int tid = threadIdx.x;

#pragma unroll
    for (int i = 0; i < 4; i++) {
        int idx = (tid + i * 256) * 4;
        *(float4*)&ctxs[idx] = *(const float4*)&g_ctx[(long)b * H_ * 1024 + idx];
    }
#pragma unroll
    for (int i = 0; i < 2; i++) {
        int idx = tid + i * 256;
        int oo = idx >> 5, c4 = idx & 31;
        *(float4*)&wsm[oo][c4 * 4] =
            *(const float4*)&w_out[((long)(ot * 16 + oo)) * HID + c4 * 4];
    }
    __syncthreads();

#pragma unroll
    for (int j = 0; j < 8; j++) {
        int idx = tid + j * 256;
        int oo = idx >> 7, hd = idx & 127;
        int h = hd >> 5, d = hd & 31;
        const float* cr = &ctxs[(h * 32 + d) * 32];
        const float* wr = &wsm[oo][h * 32];
        float s = 0.f;
#pragma unroll
        for (int e = 0; e < 32; e++) s += wr[e] * cr[e];
        long oidx = (((long)b * C_) + ot * 16 + oo) * HID + hd;
        __half hh = __float2half_rn(s);
        g_W2h[oidx] = hh;
        g_W2l[oidx] = __float2half_rn(s - __half2float(hh));
    }
}

// ---------------------------------------------------------------------------
extern "C" void kernel_launch(void* const* d_in, const int* in_sizes, int n_in,
                              void* d_out, int out_size)
{
    const float* x     = (const float*)d_in[0];
    const float* w_qkv = (const float*)d_in[1];
    const float* w_out = (const float*)d_in[2];
    const float* b_out = (const float*)d_in[3];
    float* out = (float*)d_out;

    __half *wh16, *wl16, *xf, *qf, *kb, *vb, *W2h, *W2l;
    cudaGetSymbolAddress((void**)&wh16, g_wh16);
    cudaGetSymbolAddress((void**)&wl16, g_wl16);
    cudaGetSymbolAddress((void**)&xf,   g_xf);
    cudaGetSymbolAddress((void**)&qf,   g_qf);
    cudaGetSymbolAddress((void**)&kb,   g_kb);
    cudaGetSymbolAddress((void**)&vb,   g_vb);
    cudaGetSymbolAddress((void**)&W2h,  g_W2h);
    cudaGetSymbolAddress((void**)&W2l,  g_W2l);

    cudaFuncSetAttribute(tmma<512, 0>,
                         cudaFuncAttributeMaxDynamicSharedMemorySize, SMEM_TOT);
    cudaFuncSetAttribute(tmma<128, 1>,
                         cudaFuncAttributeMaxDynamicSharedMemorySize, SMEM_TOT);

    // 0) weight split (fp16 hi/lo) + x -> fp16
    split_w16<<<(O3 * C_) / 2048, 256>>>(w_qkv, wh16, wl16);
    conv_x16<<<(int)(((long)B_ * C_ * L_) / 2048), 256>>>(x, xf);

    // 1) qkv: q -> fp16, k -> exp(k) fp16, v -> fp16
    {
        dim3 grid(L_ / 128, O3 / 128, B_);
        tmma<512, 0><<<grid, 256, SMEM_TOT>>>(
            (const uint16_t*)wh16, (const uint16_t*)wl16, (const uint16_t*)xf,
            nullptr, qf, kb, vb, nullptr,
            0L, (long)C_ * L_, 0L);
    }
    // 2) context partials (tensor-core fp16, pipelined streaming)
    {
        dim3 grid(NCH, H_, B_);
        ctx_kernel<<<grid, 128>>>();
    }
    // 3) normalize + fold
    {
        dim3 g1(H_, B_);
        ctx_norm<<<g1, 256>>>();
        dim3 g2(32, B_);
        w2g<<<g2, 256>>>(w_out);
    }
    // 4) out = W2_b @ q_b + b_out  (same fp16 pair kernel)
    {
        dim3 grid(L_ / 128, C_ / 128, B_);
        tmma<128, 1><<<grid, 256, SMEM_TOT>>>(
            (const uint16_t*)W2h, (const uint16_t*)W2l, (const uint16_t*)qf,
            out, nullptr, nullptr, nullptr, b_out,
            (long)C_ * HID, (long)HID * L_, (long)C_ * L_);
    }
}